// round 12
// baseline (speedup 1.0000x reference)
#include <cuda_runtime.h>
#include <cuda_bf16.h>

// Problem constants (fixed by the dataset)
#define B 8
#define L 2048
#define H 1024
#define C 64
#define NROWS (B * L)              // 16384
#define GRID  592                  // 148 SMs x 4 blocks: every SM gets exactly 4
#define MAXR  28                   // max rows per block (27 or 28)

// Persistent scratch (zero-initialized at module load; self-reset each launch)
__device__ float        g_acc[B * C];
__device__ unsigned int g_count;

// ---------------------------------------------------------------------------
// R12: R5's static 4-chunk warp-per-row body + balanced contiguous ranges
// (27-28 rows/block, per-SM imbalance <1% vs R5's 15.6%). Chunk 3 is
// predicated per-warp (warp-uniform branch); no dynamic loops, no per-pass
// barriers. Fence-free atomic scatter + last-block finalize.
// ---------------------------------------------------------------------------
__global__ __launch_bounds__(256, 4) void fused_kernel(
    const float* __restrict__ feature,       // [B*L, H]
    const float* __restrict__ fc_weight,     // [H]
    const float* __restrict__ fc_bias,       // [1]
    const int*   __restrict__ position_list, // [B*C*2]
    float* __restrict__ out)                 // [B*C]
{
    __shared__ float sw[H];                  // weights (4 KB)
    __shared__ float sproj[MAXR];
    __shared__ bool  is_last;
    __shared__ int   s_sink;                 // forces atomic-return consumption

    const int tid  = threadIdx.x;
    const int blk  = blockIdx.x;
    const int warp = tid >> 5;
    const int lane = tid & 31;

    // Balanced contiguous row range for this block (27 or 28 rows)
    const int lo = (int)(((long long)blk       * NROWS) / GRID);
    const int hi = (int)(((long long)(blk + 1) * NROWS) / GRID);
    const int n  = hi - lo;

    // Stage weights (4 KB) into smem
    #pragma unroll
    for (int i = tid; i < H; i += 256) sw[i] = fc_weight[i];
    __syncthreads();

    const float4* __restrict__ w4 = reinterpret_cast<const float4*>(sw);

    // --- Stage 1: 4 static chunks of 8 rows, warp-per-row; chunk 3 partial ---
    #pragma unroll
    for (int c = 0; c < 4; c++) {
        const int r = c * 8 + warp;          // row index within block range
        if (r < n) {                         // warp-uniform; chunks 0-2 full
            const float4* __restrict__ f4 = reinterpret_cast<const float4*>(
                feature + (size_t)(lo + r) * H);
            float4 a4 = make_float4(0.f, 0.f, 0.f, 0.f);
            #pragma unroll
            for (int i = 0; i < 8; i++) {
                const int idx = i * 32 + lane;       // 0..255 float4s
                float4 v = f4[idx];
                float4 w = w4[idx];
                a4.x = fmaf(v.x, w.x, a4.x);
                a4.y = fmaf(v.y, w.y, a4.y);
                a4.z = fmaf(v.z, w.z, a4.z);
                a4.w = fmaf(v.w, w.w, a4.w);
            }
            float a = (a4.x + a4.y) + (a4.z + a4.w);
            #pragma unroll
            for (int o = 16; o > 0; o >>= 1)
                a += __shfl_xor_sync(0xFFFFFFFFu, a, o);
            if (lane == 0) sproj[r] = a;
        }
    }
    __syncthreads();

    // --- Stage 2: scatter; range may straddle one batch boundary ---
    const int sb0 = lo / L;
    const int sb1 = (hi - 1) / L;
    for (int sb = sb0; sb <= sb1; sb++) {
        int wlo = lo - sb * L; if (wlo < 0) wlo = 0;   // within-batch window
        int whi = hi - sb * L; if (whi > L) whi = L;
        if (tid < C) {
            const int si  = (sb * C + tid) * 2;        // L2-hot
            const int src = position_list[si + 0];
            const int end = position_list[si + 1];
            int a = src > wlo ? src : wlo;
            int e = end < whi - 1 ? end : whi - 1;
            if (a <= e) {
                float s = 0.0f;
                const int base = sb * L - lo;          // sproj index offset
                for (int p = a; p <= e; p++)
                    s += sproj[p + base];
                // Value-returning atomic: L2 completion observed before the
                // (never-true) predicate -> release ordering for g_count
                // arrival without MEMBAR/CCTL.
                float old = atomicAdd(&g_acc[sb * C + tid], s);
                if (__float_as_uint(old) == 0xDEADBEEFu) s_sink = 1;
            }
        }
    }
    __syncthreads();   // all scatter atomics of this block have completed

    // --- Stage 3: arrive; last block finalizes ---
    if (tid == 0) {
        unsigned int prev = atomicAdd(&g_count, 1u);
        is_last = (prev == GRID - 1);
    }
    __syncthreads();

    if (is_last) {
        const float bias = fc_bias[0];
        #pragma unroll
        for (int k = 0; k < 2; k++) {
            const int i = tid + k * 256;     // 0..511
            const int src = position_list[i * 2 + 0];
            const int end = position_list[i * 2 + 1];
            const float v = __ldcg(&g_acc[i]);        // L2-coherent read
            out[i] = v / (float)(end - src + 1) + bias;
            __stcg(&g_acc[i], 0.0f);                  // reset for next launch
        }
        if (tid == 0) g_count = 0u;
    }
}

// ---------------------------------------------------------------------------
extern "C" void kernel_launch(void* const* d_in, const int* in_sizes, int n_in,
                              void* d_out, int out_size) {
    const float* feature       = (const float*)d_in[0];  // [B,L,H] f32
    const float* fc_weight     = (const float*)d_in[1];  // [1,H]   f32
    const float* fc_bias       = (const float*)d_in[2];  // [1]     f32
    const int*   position_list = (const int*)  d_in[3];  // [B,C,2] i32
    float* out = (float*)d_out;                          // [B*C,1] f32

    fused_kernel<<<GRID, 256>>>(feature, fc_weight, fc_bias,
                                position_list, out);
}

// round 13
// speedup vs baseline: 1.1208x; 1.1208x over previous
#include <cuda_runtime.h>
#include <cuda_bf16.h>

// Problem constants (fixed by the dataset)
#define B 8
#define L 2048
#define H 1024
#define C 64
#define RPB 32                     // rows per block (4 chunks x 8 warps)
#define GRID (B * L / RPB)         // 512 blocks
#define BPB (L / RPB)              // 64 blocks per batch

// Persistent scratch (zero-initialized at module load; self-reset each launch)
__device__ float        g_acc[B * C];
__device__ unsigned int g_count;

// ---------------------------------------------------------------------------
// FINAL (== R5, measured best 10.72us ~ warm-L2 LTS ceiling):
//  1) 4 statically-unrolled chunks of 8 rows, warp-per-row projection
//     (barrier-free streaming for the whole block lifetime)
//  2) scatter 32-row window into span accumulators via value-returning
//     atomicAdd (L2 completion observed before __syncthreads -> release
//     ordering for the g_count arrival, no MEMBAR/CCTL.IVALL)
//  3) last-arriving block finalizes: out = acc/count + bias, resets scratch
// ---------------------------------------------------------------------------
__global__ __launch_bounds__(256) void fused_kernel(
    const float* __restrict__ feature,       // [B*L, H]
    const float* __restrict__ fc_weight,     // [H]
    const float* __restrict__ fc_bias,       // [1]
    const int*   __restrict__ position_list, // [B*C*2]
    float* __restrict__ out)                 // [B*C]
{
    __shared__ float sw[H];
    __shared__ float sproj[RPB];
    __shared__ int   s_src[C], s_end[C];
    __shared__ bool  is_last;
    __shared__ int   s_sink;                 // forces atomic-return consumption

    const int tid   = threadIdx.x;
    const int blk   = blockIdx.x;
    const int batch = blk / BPB;
    const int row0  = (blk % BPB) * RPB;

    // Stage weights (4 KB) and this batch's spans (512 B) into smem
    #pragma unroll
    for (int i = tid; i < H; i += 256) sw[i] = fc_weight[i];
    if (tid < C) {
        const int si = (batch * C + tid) * 2;
        s_src[tid] = position_list[si + 0];
        s_end[tid] = position_list[si + 1];
    }
    __syncthreads();

    const int warp = tid >> 5;
    const int lane = tid & 31;
    const float4* __restrict__ w4 = reinterpret_cast<const float4*>(sw);

    // --- Stage 1: 4 chunks of 8 rows, warp-per-row ---
    #pragma unroll
    for (int c = 0; c < 4; c++) {
        const int r   = c * 8 + warp;                    // 0..31 within block
        const int row = batch * L + row0 + r;            // global row
        const float4* __restrict__ f4 =
            reinterpret_cast<const float4*>(feature + (size_t)row * H);

        float acc = 0.0f;
        #pragma unroll
        for (int i = 0; i < 8; i++) {
            const int idx = i * 32 + lane;               // 0..255 float4s
            float4 v = f4[idx];
            float4 w = w4[idx];
            acc = fmaf(v.x, w.x, acc);
            acc = fmaf(v.y, w.y, acc);
            acc = fmaf(v.z, w.z, acc);
            acc = fmaf(v.w, w.w, acc);
        }
        #pragma unroll
        for (int o = 16; o > 0; o >>= 1)
            acc += __shfl_xor_sync(0xFFFFFFFFu, acc, o);
        if (lane == 0) sproj[r] = acc;
    }
    __syncthreads();

    // --- Stage 2: scatter into span accumulators (threads 0..63) ---
    if (tid < C) {
        const int src = s_src[tid];
        const int end = s_end[tid];
        // overlap of [src,end] with this block's rows [row0, row0+RPB-1]
        int lo = src - row0; if (lo < 0) lo = 0;
        int hi = end - row0; if (hi > RPB - 1) hi = RPB - 1;
        if (lo <= hi) {
            float s = 0.0f;
            #pragma unroll
            for (int r = 0; r < RPB; r++)
                if (r >= lo && r <= hi) s += sproj[r];
            // Value-returning atomic: L2 completion observed before the
            // (never-true) predicate below can be evaluated.
            float old = atomicAdd(&g_acc[batch * C + tid], s);
            if (__float_as_uint(old) == 0xDEADBEEFu) s_sink = 1;
        }
    }
    __syncthreads();   // all scatter atomics of this block have completed

    // --- Stage 3: arrive; last block finalizes ---
    if (tid == 0) {
        unsigned int prev = atomicAdd(&g_count, 1u);
        is_last = (prev == GRID - 1);
    }
    __syncthreads();

    if (is_last) {
        const float bias = fc_bias[0];
        #pragma unroll
        for (int k = 0; k < 2; k++) {
            const int i = tid + k * 256;     // 0..511
            const int src = position_list[i * 2 + 0];
            const int end = position_list[i * 2 + 1];
            const float v = __ldcg(&g_acc[i]);        // L2-coherent read
            out[i] = v / (float)(end - src + 1) + bias;
            __stcg(&g_acc[i], 0.0f);                  // reset for next launch
        }
        if (tid == 0) g_count = 0u;
    }
}

// ---------------------------------------------------------------------------
extern "C" void kernel_launch(void* const* d_in, const int* in_sizes, int n_in,
                              void* d_out, int out_size) {
    const float* feature       = (const float*)d_in[0];  // [B,L,H] f32
    const float* fc_weight     = (const float*)d_in[1];  // [1,H]   f32
    const float* fc_bias       = (const float*)d_in[2];  // [1]     f32
    const int*   position_list = (const int*)  d_in[3];  // [B,C,2] i32
    float* out = (float*)d_out;                          // [B*C,1] f32

    fused_kernel<<<GRID, 256>>>(feature, fc_weight, fc_bias,
                                position_list, out);
}

// round 14
// speedup vs baseline: 1.1875x; 1.0595x over previous
#include <cuda_runtime.h>
#include <cuda_bf16.h>

// Problem constants (fixed by the dataset)
#define B 8
#define L 2048
#define H 1024
#define C 64
#define RPB 32                     // rows per block (4 chunks x 8 warps)
#define GRID (B * L / RPB)         // 512 blocks
#define BPB (L / RPB)              // 64 blocks per batch

// Persistent scratch (zero-initialized at module load; self-reset each launch)
__device__ float        g_acc[B * C];
__device__ unsigned int g_count;

// ---------------------------------------------------------------------------
// R14 (final form): R5's measured-best structure +
//   - chunk-0 prefetch: 16 LDG.128/warp issued BEFORE the weight-staging
//     barrier, so the feature stream starts during staging
//   - position_list read directly in stage 2 (L2-hot), no pre-sync staging
// Epilogue: fence-free value-returning-atomic scatter + last-block finalize.
// ---------------------------------------------------------------------------
__global__ __launch_bounds__(256) void fused_kernel(
    const float* __restrict__ feature,       // [B*L, H]
    const float* __restrict__ fc_weight,     // [H]
    const float* __restrict__ fc_bias,       // [1]
    const int*   __restrict__ position_list, // [B*C*2]
    float* __restrict__ out)                 // [B*C]
{
    __shared__ float sw[H];
    __shared__ float sproj[RPB];
    __shared__ bool  is_last;
    __shared__ int   s_sink;                 // forces atomic-return consumption

    const int tid   = threadIdx.x;
    const int blk   = blockIdx.x;
    const int batch = blk / BPB;
    const int row0  = (blk % BPB) * RPB;
    const int warp  = tid >> 5;
    const int lane  = tid & 31;

    // Chunk-0 prefetch: issue 4 float4 loads per lane BEFORE the barrier.
    // These are independent of the weights, so they stream during staging.
    const float4* __restrict__ f4_0 = reinterpret_cast<const float4*>(
        feature + (size_t)(batch * L + row0 + warp) * H);
    float4 p0 = f4_0[0 * 32 + lane];
    float4 p1 = f4_0[1 * 32 + lane];
    float4 p2 = f4_0[2 * 32 + lane];
    float4 p3 = f4_0[3 * 32 + lane];

    // Stage weights (4 KB) into smem
    #pragma unroll
    for (int i = tid; i < H; i += 256) sw[i] = fc_weight[i];
    __syncthreads();

    const float4* __restrict__ w4 = reinterpret_cast<const float4*>(sw);

    // --- Stage 1: 4 chunks of 8 rows, warp-per-row ---
    #pragma unroll
    for (int c = 0; c < 4; c++) {
        const float4* __restrict__ f4 = reinterpret_cast<const float4*>(
            feature + (size_t)(batch * L + row0 + c * 8 + warp) * H);

        float acc = 0.0f;
        if (c == 0) {
            // First 4 quads come from the prefetch registers
            {
                float4 w = w4[0 * 32 + lane];
                acc = fmaf(p0.x, w.x, acc); acc = fmaf(p0.y, w.y, acc);
                acc = fmaf(p0.z, w.z, acc); acc = fmaf(p0.w, w.w, acc);
            }
            {
                float4 w = w4[1 * 32 + lane];
                acc = fmaf(p1.x, w.x, acc); acc = fmaf(p1.y, w.y, acc);
                acc = fmaf(p1.z, w.z, acc); acc = fmaf(p1.w, w.w, acc);
            }
            {
                float4 w = w4[2 * 32 + lane];
                acc = fmaf(p2.x, w.x, acc); acc = fmaf(p2.y, w.y, acc);
                acc = fmaf(p2.z, w.z, acc); acc = fmaf(p2.w, w.w, acc);
            }
            {
                float4 w = w4[3 * 32 + lane];
                acc = fmaf(p3.x, w.x, acc); acc = fmaf(p3.y, w.y, acc);
                acc = fmaf(p3.z, w.z, acc); acc = fmaf(p3.w, w.w, acc);
            }
            #pragma unroll
            for (int i = 4; i < 8; i++) {
                const int idx = i * 32 + lane;
                float4 v = f4[idx];
                float4 w = w4[idx];
                acc = fmaf(v.x, w.x, acc); acc = fmaf(v.y, w.y, acc);
                acc = fmaf(v.z, w.z, acc); acc = fmaf(v.w, w.w, acc);
            }
        } else {
            #pragma unroll
            for (int i = 0; i < 8; i++) {
                const int idx = i * 32 + lane;
                float4 v = f4[idx];
                float4 w = w4[idx];
                acc = fmaf(v.x, w.x, acc); acc = fmaf(v.y, w.y, acc);
                acc = fmaf(v.z, w.z, acc); acc = fmaf(v.w, w.w, acc);
            }
        }
        #pragma unroll
        for (int o = 16; o > 0; o >>= 1)
            acc += __shfl_xor_sync(0xFFFFFFFFu, acc, o);
        if (lane == 0) sproj[c * 8 + warp] = acc;
    }
    __syncthreads();

    // --- Stage 2: scatter into span accumulators (threads 0..63) ---
    if (tid < C) {
        const int si  = (batch * C + tid) * 2;   // L2-hot global read
        const int src = position_list[si + 0];
        const int end = position_list[si + 1];
        // overlap of [src,end] with this block's rows [row0, row0+RPB-1]
        int lo = src - row0; if (lo < 0) lo = 0;
        int hi = end - row0; if (hi > RPB - 1) hi = RPB - 1;
        if (lo <= hi) {
            float s = 0.0f;
            #pragma unroll
            for (int r = 0; r < RPB; r++)
                if (r >= lo && r <= hi) s += sproj[r];
            // Value-returning atomic: L2 completion observed before the
            // (never-true) predicate -> release ordering for the g_count
            // arrival without MEMBAR/CCTL.IVALL.
            float old = atomicAdd(&g_acc[batch * C + tid], s);
            if (__float_as_uint(old) == 0xDEADBEEFu) s_sink = 1;
        }
    }
    __syncthreads();   // all scatter atomics of this block have completed

    // --- Stage 3: arrive; last block finalizes ---
    if (tid == 0) {
        unsigned int prev = atomicAdd(&g_count, 1u);
        is_last = (prev == GRID - 1);
    }
    __syncthreads();

    if (is_last) {
        const float bias = fc_bias[0];
        #pragma unroll
        for (int k = 0; k < 2; k++) {
            const int i = tid + k * 256;     // 0..511
            const int src = position_list[i * 2 + 0];
            const int end = position_list[i * 2 + 1];
            const float v = __ldcg(&g_acc[i]);        // L2-coherent read
            out[i] = v / (float)(end - src + 1) + bias;
            __stcg(&g_acc[i], 0.0f);                  // reset for next launch
        }
        if (tid == 0) g_count = 0u;
    }
}

// ---------------------------------------------------------------------------
extern "C" void kernel_launch(void* const* d_in, const int* in_sizes, int n_in,
                              void* d_out, int out_size) {
    const float* feature       = (const float*)d_in[0];  // [B,L,H] f32
    const float* fc_weight     = (const float*)d_in[1];  // [1,H]   f32
    const float* fc_bias       = (const float*)d_in[2];  // [1]     f32
    const int*   position_list = (const int*)  d_in[3];  // [B,C,2] i32
    float* out = (float*)d_out;                          // [B*C,1] f32

    fused_kernel<<<GRID, 256>>>(feature, fc_weight, fc_bias,
                                position_list, out);
}